// round 5
// baseline (speedup 1.0000x reference)
#include <cuda_runtime.h>

#define H 1024
#define S 65536
#define ROWS_PER_BLOCK 8
#define NB (S / ROWS_PER_BLOCK)   // 8192 blocks for the streaming pass
#define NB2 64
#define CHUNK (S / NB2)           // 1024 elements per epilogue block

// Scratch (no allocations allowed in kernel_launch)
__device__ float g_v[H];
__device__ float g_c;
__device__ float g_scores[S];
__device__ float g_blockmax[NB];
__device__ float g_blocksum[NB2];

// ---------------------------------------------------------------------------
// k1: v[j] = sum_i hidden[i] * W[i*H + j]   (blocks 0..3, 256 j's each)
//     c    = b . hidden                      (block 4)
// ---------------------------------------------------------------------------
__global__ void k1_compute_v(const float* __restrict__ hidden,
                             const float* __restrict__ W,
                             const float* __restrict__ b) {
    __shared__ float sh[H];
    const int tid = threadIdx.x;
    for (int i = tid; i < H; i += 256) sh[i] = hidden[i];
    __syncthreads();

    if (blockIdx.x < 4) {
        const int j = blockIdx.x * 256 + tid;
        // 4 accumulators to break the FMA dependency chain; loads coalesced in j.
        float a0 = 0.f, a1 = 0.f, a2 = 0.f, a3 = 0.f;
        #pragma unroll 4
        for (int i = 0; i < H; i += 4) {
            a0 = fmaf(sh[i + 0], W[(size_t)(i + 0) * H + j], a0);
            a1 = fmaf(sh[i + 1], W[(size_t)(i + 1) * H + j], a1);
            a2 = fmaf(sh[i + 2], W[(size_t)(i + 2) * H + j], a2);
            a3 = fmaf(sh[i + 3], W[(size_t)(i + 3) * H + j], a3);
        }
        g_v[j] = (a0 + a1) + (a2 + a3);
    } else {
        __shared__ float red[256];
        float acc = 0.f;
        for (int i = tid; i < H; i += 256) acc = fmaf(b[i], sh[i], acc);
        red[tid] = acc;
        __syncthreads();
        for (int s = 128; s > 0; s >>= 1) {
            if (tid < s) red[tid] += red[tid + s];
            __syncthreads();
        }
        if (tid == 0) g_c = red[0];
    }
}

// ---------------------------------------------------------------------------
// k2: scores[row] = enc[row,:] . v + c ; per-block max.
// One warp per row, float4 loads, v staged in shared memory.
// This is the 256 MB streaming pass — the whole kernel's roofline.
// ---------------------------------------------------------------------------
__global__ __launch_bounds__(256) void k2_scores(const float* __restrict__ enc) {
    __shared__ float4 sv[H / 4];
    __shared__ float wmax[ROWS_PER_BLOCK];
    const int tid = threadIdx.x;

    for (int i = tid; i < H / 4; i += 256)
        sv[i] = reinterpret_cast<const float4*>(g_v)[i];
    __syncthreads();

    const int warp = tid >> 5;
    const int lane = tid & 31;
    const int row  = blockIdx.x * ROWS_PER_BLOCK + warp;
    const float4* __restrict__ r4 =
        reinterpret_cast<const float4*>(enc + (size_t)row * H);

    float acc = 0.f;
    #pragma unroll
    for (int k = 0; k < 8; k++) {                // 8 independent 16B loads -> MLP=8
        float4 a  = r4[k * 32 + lane];
        float4 vv = sv[k * 32 + lane];
        acc = fmaf(a.x, vv.x, acc);
        acc = fmaf(a.y, vv.y, acc);
        acc = fmaf(a.z, vv.z, acc);
        acc = fmaf(a.w, vv.w, acc);
    }
    #pragma unroll
    for (int o = 16; o > 0; o >>= 1)
        acc += __shfl_xor_sync(0xffffffffu, acc, o);

    if (lane == 0) {
        float sc = acc + g_c;
        g_scores[row] = sc;
        wmax[warp] = sc;
    }
    __syncthreads();
    if (tid == 0) {
        float m = wmax[0];
        #pragma unroll
        for (int w = 1; w < ROWS_PER_BLOCK; w++) m = fmaxf(m, wmax[w]);
        g_blockmax[blockIdx.x] = m;
    }
}

// ---------------------------------------------------------------------------
// k3: each block (redundantly, deterministically) reduces the 8192 block
//     maxes, then writes exp(s - max) to out for its 1024-chunk + partial sum.
// ---------------------------------------------------------------------------
__global__ __launch_bounds__(256) void k3_exp(float* __restrict__ out) {
    __shared__ float red[256];
    const int tid = threadIdx.x;

    float m = -3.402823466e38f;
    for (int i = tid; i < NB; i += 256) m = fmaxf(m, g_blockmax[i]);
    red[tid] = m;
    __syncthreads();
    for (int s = 128; s > 0; s >>= 1) {
        if (tid < s) red[tid] = fmaxf(red[tid], red[tid + s]);
        __syncthreads();
    }
    const float gmax = red[0];
    __syncthreads();

    const int base = blockIdx.x * CHUNK;
    float psum = 0.f;
    for (int i = tid; i < CHUNK; i += 256) {
        float e = __expf(g_scores[base + i] - gmax);
        out[base + i] = e;
        psum += e;
    }
    red[tid] = psum;
    __syncthreads();
    for (int s = 128; s > 0; s >>= 1) {
        if (tid < s) red[tid] += red[tid + s];
        __syncthreads();
    }
    if (tid == 0) g_blocksum[blockIdx.x] = red[0];
}

// ---------------------------------------------------------------------------
// k4: reduce the 64 partial sums (deterministic tree), scale out.
// ---------------------------------------------------------------------------
__global__ __launch_bounds__(256) void k4_scale(float* __restrict__ out) {
    __shared__ float red[64];
    const int tid = threadIdx.x;
    if (tid < 64) red[tid] = g_blocksum[tid];
    __syncthreads();
    for (int s = 32; s > 0; s >>= 1) {
        if (tid < s) red[tid] += red[tid + s];
        __syncthreads();
    }
    const float inv = 1.0f / red[0];
    const int base = blockIdx.x * CHUNK;
    for (int i = tid; i < CHUNK; i += 256) out[base + i] *= inv;
}

// ---------------------------------------------------------------------------
extern "C" void kernel_launch(void* const* d_in, const int* in_sizes, int n_in,
                              void* d_out, int out_size) {
    const float* hidden = (const float*)d_in[0];   // [H]
    const float* enc    = (const float*)d_in[1];   // [S, H]
    const float* W      = (const float*)d_in[2];   // [H, H]
    const float* b      = (const float*)d_in[3];   // [H]
    float* out = (float*)d_out;                    // [1,1,S] fp32

    k1_compute_v<<<5, 256>>>(hidden, W, b);
    k2_scores<<<NB, 256>>>(enc);
    k3_exp<<<NB2, 256>>>(out);
    k4_scale<<<NB2, 256>>>(out);
}

// round 6
// speedup vs baseline: 2.0654x; 2.0654x over previous
#include <cuda_runtime.h>

#define H 1024
#define S 65536

// k2 geometry: 16 rows per block (one warp per row), 512 threads
#define RPB 16
#define NB2 (S / RPB)          // 4096 streaming blocks

// k1 geometry: 32 i-slices x 4 j-blocks = 128 partial blocks
#define ISLICES 32
#define IROWS   (H / ISLICES)  // 32 rows of W per partial block

// epilogue geometry
#define EB 256                 // epilogue blocks
#define ECHUNK (S / EB)        // 256 elements per block

// Scratch (device globals — no allocation allowed)
__device__ float    g_vpart[ISLICES * H];
__device__ float    g_v[H];
__device__ float    g_c;
__device__ float    g_scores[S];
__device__ unsigned g_maxu;            // monotonic-uint encoded global max
__device__ float    g_blocksum[EB];

// float <-> monotonic unsigned (order-preserving); atomicMax-able, deterministic
__device__ __forceinline__ unsigned fenc(float f) {
    unsigned u = __float_as_uint(f);
    return (u & 0x80000000u) ? ~u : (u | 0x80000000u);
}
__device__ __forceinline__ float fdec(unsigned u) {
    unsigned b = (u & 0x80000000u) ? (u & 0x7fffffffu) : ~u;
    return __uint_as_float(b);
}

// ---------------------------------------------------------------------------
// k1: partial v over i-slices.  blocks 0..127: g_vpart[slice][j] for 256 j's.
//     block 128: c = b.h  and reset g_maxu.
// W read (4 MB) now spread across 128 SMs instead of 4.
// ---------------------------------------------------------------------------
__global__ __launch_bounds__(256) void k1_partial_v(const float* __restrict__ hidden,
                                                    const float* __restrict__ W,
                                                    const float* __restrict__ b) {
    const int tid = threadIdx.x;
    if (blockIdx.x < ISLICES * 4) {
        const int islice = blockIdx.x >> 2;
        const int j      = ((blockIdx.x & 3) << 8) + tid;
        const int i0     = islice * IROWS;
        float a0 = 0.f, a1 = 0.f, a2 = 0.f, a3 = 0.f;
        #pragma unroll
        for (int i = 0; i < IROWS; i += 4) {
            a0 = fmaf(hidden[i0 + i + 0], W[(size_t)(i0 + i + 0) * H + j], a0);
            a1 = fmaf(hidden[i0 + i + 1], W[(size_t)(i0 + i + 1) * H + j], a1);
            a2 = fmaf(hidden[i0 + i + 2], W[(size_t)(i0 + i + 2) * H + j], a2);
            a3 = fmaf(hidden[i0 + i + 3], W[(size_t)(i0 + i + 3) * H + j], a3);
        }
        g_vpart[islice * H + j] = (a0 + a1) + (a2 + a3);
    } else {
        __shared__ float red[256];
        float acc = 0.f;
        for (int i = tid; i < H; i += 256) acc = fmaf(b[i], hidden[i], acc);
        red[tid] = acc;
        __syncthreads();
        for (int s = 128; s > 0; s >>= 1) {
            if (tid < s) red[tid] += red[tid + s];
            __syncthreads();
        }
        if (tid == 0) { g_c = red[0]; g_maxu = 0u; }   // 0 == encoding below -inf
    }
}

// k1b: v[j] = sum over 32 slices (deterministic fixed order). 4 blocks x 256.
__global__ __launch_bounds__(256) void k1b_reduce_v() {
    const int j = blockIdx.x * 256 + threadIdx.x;
    float acc = 0.f;
    #pragma unroll
    for (int s = 0; s < ISLICES; s++) acc += g_vpart[s * H + j];
    g_v[j] = acc;
}

// ---------------------------------------------------------------------------
// k2: scores[row] = enc[row,:].v + c ; one atomicMax per block (deterministic).
// The 256 MB streaming pass — one warp per row, float4, MLP=8/warp.
// ---------------------------------------------------------------------------
__global__ __launch_bounds__(512) void k2_scores(const float* __restrict__ enc) {
    __shared__ float4 sv[H / 4];
    __shared__ float wmax[RPB];
    const int tid = threadIdx.x;

    if (tid < H / 4) sv[tid] = reinterpret_cast<const float4*>(g_v)[tid];
    __syncthreads();

    const int warp = tid >> 5;
    const int lane = tid & 31;
    const int row  = blockIdx.x * RPB + warp;
    const float4* __restrict__ r4 =
        reinterpret_cast<const float4*>(enc + (size_t)row * H);

    float acc = 0.f;
    #pragma unroll
    for (int k = 0; k < 8; k++) {               // 8 independent 16B loads
        float4 a  = r4[k * 32 + lane];
        float4 vv = sv[k * 32 + lane];
        acc = fmaf(a.x, vv.x, acc);
        acc = fmaf(a.y, vv.y, acc);
        acc = fmaf(a.z, vv.z, acc);
        acc = fmaf(a.w, vv.w, acc);
    }
    #pragma unroll
    for (int o = 16; o > 0; o >>= 1)
        acc += __shfl_xor_sync(0xffffffffu, acc, o);

    if (lane == 0) {
        float sc = acc + g_c;
        g_scores[row] = sc;
        wmax[warp] = sc;
    }
    __syncthreads();
    if (tid == 0) {
        float m = wmax[0];
        #pragma unroll
        for (int w = 1; w < RPB; w++) m = fmaxf(m, wmax[w]);
        atomicMax(&g_maxu, fenc(m));            // order-independent => deterministic
    }
}

// ---------------------------------------------------------------------------
// k3: exp(s - gmax) -> out, per-block partial sum. 256 blocks x 256 (1 elem/thr).
// ---------------------------------------------------------------------------
__global__ __launch_bounds__(256) void k3_exp(float* __restrict__ out) {
    __shared__ float red[256];
    const int tid  = threadIdx.x;
    const int base = blockIdx.x * ECHUNK;
    const float gmax = fdec(g_maxu);

    float e = __expf(g_scores[base + tid] - gmax);
    out[base + tid] = e;

    red[tid] = e;
    __syncthreads();
    for (int s = 128; s > 0; s >>= 1) {
        if (tid < s) red[tid] += red[tid + s];
        __syncthreads();
    }
    if (tid == 0) g_blocksum[blockIdx.x] = red[0];
}

// ---------------------------------------------------------------------------
// k4: redundant deterministic reduce of 256 partials, then scale (1 elem/thr).
// ---------------------------------------------------------------------------
__global__ __launch_bounds__(256) void k4_scale(float* __restrict__ out) {
    __shared__ float red[256];
    const int tid = threadIdx.x;
    red[tid] = g_blocksum[tid];
    __syncthreads();
    for (int s = 128; s > 0; s >>= 1) {
        if (tid < s) red[tid] += red[tid + s];
        __syncthreads();
    }
    const float inv = 1.0f / red[0];
    const int base = blockIdx.x * ECHUNK;
    out[base + tid] *= inv;
}

// ---------------------------------------------------------------------------
extern "C" void kernel_launch(void* const* d_in, const int* in_sizes, int n_in,
                              void* d_out, int out_size) {
    const float* hidden = (const float*)d_in[0];   // [H]
    const float* enc    = (const float*)d_in[1];   // [S, H]
    const float* W      = (const float*)d_in[2];   // [H, H]
    const float* b      = (const float*)d_in[3];   // [H]
    float* out = (float*)d_out;                    // [1,1,S] fp32

    k1_partial_v<<<ISLICES * 4 + 1, 256>>>(hidden, W, b);
    k1b_reduce_v<<<H / 256, 256>>>();
    k2_scores<<<NB2, 512>>>(enc);
    k3_exp<<<EB, 256>>>(out);
    k4_scale<<<EB, 256>>>(out);
}

// round 7
// speedup vs baseline: 2.1201x; 1.0265x over previous
#include <cuda_runtime.h>

#define H 1024
#define S 65536
#define NBLK 148
#define THR  1024
#define NWARP 32
#define CHUNK 443              // ceil(S / NBLK); 148*443 = 65564 >= 65536

#define NSL   128              // W i-slices (8 rows each)
#define P2BLK 16               // blocks doing the v reduction (64 j each)

// ---- device scratch (no allocation allowed) ----
__device__ float    g_vpart[NSL * H];
__device__ float    g_v[H];
__device__ float    g_bm[NBLK];
__device__ float    g_bs[NBLK];
__device__ unsigned g_ctr;
__device__ volatile unsigned g_flag;

#define NEG_INF (-3.402823466e38f)

// ---------------------------------------------------------------------------
// k0: reset the grid-barrier state. Runs first in the graph each replay, so
// the reset is stream-ordered w.r.t. all spinners (no reset race / deadlock).
// ---------------------------------------------------------------------------
__global__ void k0_reset() { g_ctr = 0u; g_flag = 0u; }

// ---------------------------------------------------------------------------
// Grid barrier: arrivals on g_ctr, release via monotonic g_flag = phase.
// Spin on a plain volatile load (reads don't serialize at the LTS the way
// atomics do); nanosleep backoff keeps poll pressure low.
// ---------------------------------------------------------------------------
__device__ __forceinline__ void gbar(unsigned phase) {
    __syncthreads();
    if (threadIdx.x == 0) {
        __threadfence();                         // release our writes
        unsigned old = atomicAdd(&g_ctr, 1u);
        if (old == phase * NBLK - 1u) {
            g_flag = phase;                      // last arriver releases
            __threadfence();
        } else {
            while (g_flag < phase) __nanosleep(64);
        }
        __threadfence();                         // acquire
    }
    __syncthreads();
}

// ---------------------------------------------------------------------------
// The whole problem in one persistent kernel.
//   P1: v-partials over 128 W slices (8 rows each)       [blocks 0..127]
//   P2: v[j] = fixed-order sum of 128 partials           [blocks 0..15]
//   P3: stream enc (256 MB), warp-per-row dot, scores -> SMEM,
//       per-warp online (m, s), block merge -> g_bm/g_bs [all blocks]
//   P4: redundant deterministic 148-pair merge, exp+scale from SMEM
// Note: the reference's  + b.hidden  is a constant shift -> softmax-invariant
// -> dropped entirely.
// ---------------------------------------------------------------------------
__global__ __launch_bounds__(THR, 1) void kmain(const float* __restrict__ hidden,
                                                const float* __restrict__ enc,
                                                const float* __restrict__ W,
                                                float* __restrict__ out) {
    __shared__ float sv[H];           // v staged for phase 3
    __shared__ float ssc[CHUNK + 1];  // this block's scores (never hit gmem)
    __shared__ float p2[P2BLK * 64];  // phase-2 reduction workspace
    __shared__ float smw[NWARP], ssw[NWARP];
    __shared__ float s_gm, s_gs;

    const int b    = blockIdx.x;
    const int tid  = threadIdx.x;
    const int warp = tid >> 5;
    const int lane = tid & 31;

    // ---------------- Phase 1: v partials ----------------
    if (b < NSL) {
        const int i0 = b << 3;                   // 8 rows of W per slice
        const int j  = tid;
        float acc = 0.f;
        #pragma unroll
        for (int k = 0; k < 8; k++)
            acc = fmaf(__ldg(&hidden[i0 + k]), W[(size_t)(i0 + k) * H + j], acc);
        g_vpart[b * H + j] = acc;
    }
    gbar(1);

    // ---------------- Phase 2: reduce v ----------------
    if (b < P2BLK) {
        const int jl   = tid & 63;
        const int part = tid >> 6;               // 16 parts x 8 slices
        const int j    = b * 64 + jl;
        float acc = 0.f;
        #pragma unroll
        for (int s = 0; s < 8; s++)
            acc += __ldcg(&g_vpart[(part * 8 + s) * H + j]);
        p2[part * 64 + jl] = acc;
        for (int hh = 8; hh > 0; hh >>= 1) {
            __syncthreads();
            if (part < hh) p2[part * 64 + jl] += p2[(part + hh) * 64 + jl];
        }
        __syncthreads();
        if (part == 0) g_v[j] = p2[jl];
    }
    gbar(2);

    // ---------------- Phase 3: stream enc ----------------
    if (tid < H / 4)
        reinterpret_cast<float4*>(sv)[tid] =
            __ldcg(reinterpret_cast<const float4*>(g_v) + tid);
    __syncthreads();

    const int start = b * CHUNK;
    const int end   = (start + CHUNK < S) ? start + CHUNK : S;

    float m = NEG_INF, s = 0.f;
    for (int r = start + warp; r < end; r += NWARP) {
        const float4* __restrict__ r4 =
            reinterpret_cast<const float4*>(enc + (size_t)r * H);
        const float4* __restrict__ v4 = reinterpret_cast<const float4*>(sv);
        float acc = 0.f;
        #pragma unroll
        for (int k = 0; k < 8; k++) {            // 8 independent 16B loads/lane
            float4 a  = r4[k * 32 + lane];
            float4 vv = v4[k * 32 + lane];
            acc = fmaf(a.x, vv.x, acc);
            acc = fmaf(a.y, vv.y, acc);
            acc = fmaf(a.z, vv.z, acc);
            acc = fmaf(a.w, vv.w, acc);
        }
        #pragma unroll
        for (int o = 16; o > 0; o >>= 1)
            acc += __shfl_xor_sync(0xffffffffu, acc, o);
        if (lane == 0) ssc[r - start] = acc;
        float nm = fmaxf(m, acc);                // online softmax update
        s = s * __expf(m - nm) + __expf(acc - nm);
        m = nm;
    }
    if (lane == 0) { smw[warp] = m; ssw[warp] = s; }
    __syncthreads();

    if (warp == 0) {                             // fixed-tree block merge
        float mm = smw[lane], sss = ssw[lane];
        #pragma unroll
        for (int o = 16; o > 0; o >>= 1) {
            float om = __shfl_xor_sync(0xffffffffu, mm, o);
            float os = __shfl_xor_sync(0xffffffffu, sss, o);
            float nm = fmaxf(mm, om);
            sss = sss * __expf(mm - nm) + os * __expf(om - nm);
            mm = nm;
        }
        if (lane == 0) { g_bm[b] = mm; g_bs[b] = sss; }
    }
    gbar(3);

    // ---------------- Phase 4: global merge + epilogue ----------------
    if (warp == 0) {                             // every block, redundantly
        float mm = NEG_INF, sss = 0.f;
        #pragma unroll
        for (int q = 0; q < 5; q++) {            // fixed order: deterministic
            int idx = lane + q * 32;
            if (idx < NBLK) {
                float om = __ldcg(&g_bm[idx]);
                float os = __ldcg(&g_bs[idx]);
                float nm = fmaxf(mm, om);
                sss = sss * __expf(mm - nm) + os * __expf(om - nm);
                mm = nm;
            }
        }
        #pragma unroll
        for (int o = 16; o > 0; o >>= 1) {
            float om = __shfl_xor_sync(0xffffffffu, mm, o);
            float os = __shfl_xor_sync(0xffffffffu, sss, o);
            float nm = fmaxf(mm, om);
            sss = sss * __expf(mm - nm) + os * __expf(om - nm);
            mm = nm;
        }
        if (lane == 0) { s_gm = mm; s_gs = sss; }
    }
    __syncthreads();

    const float gm  = s_gm;
    const float inv = 1.0f / s_gs;
    const int i = start + tid;                   // CHUNK=443 < 1024: one iter
    if (i < end) out[i] = __expf(ssc[i - start] - gm) * inv;
}

// ---------------------------------------------------------------------------
extern "C" void kernel_launch(void* const* d_in, const int* in_sizes, int n_in,
                              void* d_out, int out_size) {
    const float* hidden = (const float*)d_in[0];   // [H]
    const float* enc    = (const float*)d_in[1];   // [S, H]
    const float* W      = (const float*)d_in[2];   // [H, H]
    // d_in[3] = b : softmax-shift-invariant, unused
    float* out = (float*)d_out;                    // [1,1,S] fp32

    k0_reset<<<1, 1>>>();
    kmain<<<NBLK, THR>>>(hidden, enc, W, out);
}

// round 8
// speedup vs baseline: 2.2181x; 1.0462x over previous
#include <cuda_runtime.h>

#define H 1024
#define S 65536
#define NBLK 148
#define THR  1024
#define NWARP 32
#define CHUNK 443              // ceil(S / NBLK); 148*443 = 65564 >= 65536

#define NSL   128              // W i-slices (8 rows each)
#define P2BLK 16               // blocks doing the v reduction (64 j each)

// ---- device scratch (no allocation allowed) ----
__device__ float    g_vpart[NSL * H];
__device__ float    g_v[H];
__device__ float    g_bm[NBLK];
__device__ float    g_bs[NBLK];
__device__ unsigned g_ctr;
__device__ volatile unsigned g_flag;

#define NEG_INF (-3.402823466e38f)

// ---------------------------------------------------------------------------
// k0: reset grid-barrier state; stream-ordered before kmain, so no reset race.
// ---------------------------------------------------------------------------
__global__ void k0_reset() { g_ctr = 0u; g_flag = 0u; }

// ---------------------------------------------------------------------------
// Grid barrier: arrivals on g_ctr, release via monotonic g_flag = phase.
// ---------------------------------------------------------------------------
__device__ __forceinline__ void gbar(unsigned phase) {
    __syncthreads();
    if (threadIdx.x == 0) {
        __threadfence();
        unsigned old = atomicAdd(&g_ctr, 1u);
        if (old == phase * NBLK - 1u) {
            g_flag = phase;
            __threadfence();
        } else {
            while (g_flag < phase) __nanosleep(64);
        }
        __threadfence();
    }
    __syncthreads();
}

// ---------------------------------------------------------------------------
// One persistent kernel. P3 is software-pipelined: row r's loads are issued
// BEFORE row r-1's shuffle-reduce + online-softmax, hiding the ~300-cycle
// compute tail under memory latency so each warp always has loads in flight.
//   (b . hidden is a softmax-invariant constant shift -> dropped.)
// ---------------------------------------------------------------------------
__global__ __launch_bounds__(THR, 1) void kmain(const float* __restrict__ hidden,
                                                const float* __restrict__ enc,
                                                const float* __restrict__ W,
                                                float* __restrict__ out) {
    __shared__ float sv[H];           // v staged for phase 3
    __shared__ float ssc[CHUNK + 1];  // this block's scores (never hit gmem)
    __shared__ float p2[P2BLK * 64];  // phase-2 reduction workspace
    __shared__ float smw[NWARP], ssw[NWARP];
    __shared__ float s_gm, s_gs;

    const int b    = blockIdx.x;
    const int tid  = threadIdx.x;
    const int warp = tid >> 5;
    const int lane = tid & 31;

    // ---------------- Phase 1: v partials (128 slices x 8 W-rows) ---------
    if (b < NSL) {
        const int i0 = b << 3;
        const int j  = tid;
        float acc = 0.f;
        #pragma unroll
        for (int k = 0; k < 8; k++)
            acc = fmaf(__ldg(&hidden[i0 + k]), W[(size_t)(i0 + k) * H + j], acc);
        g_vpart[b * H + j] = acc;
    }
    gbar(1);

    // ---------------- Phase 2: reduce v ----------------
    if (b < P2BLK) {
        const int jl   = tid & 63;
        const int part = tid >> 6;
        const int j    = b * 64 + jl;
        float acc = 0.f;
        #pragma unroll
        for (int s = 0; s < 8; s++)
            acc += __ldcg(&g_vpart[(part * 8 + s) * H + j]);
        p2[part * 64 + jl] = acc;
        for (int hh = 8; hh > 0; hh >>= 1) {
            __syncthreads();
            if (part < hh) p2[part * 64 + jl] += p2[(part + hh) * 64 + jl];
        }
        __syncthreads();
        if (part == 0) g_v[j] = p2[jl];
    }
    gbar(2);

    // ---------------- Phase 3: stream enc (software-pipelined) -------------
    if (tid < H / 4)
        reinterpret_cast<float4*>(sv)[tid] =
            __ldcg(reinterpret_cast<const float4*>(g_v) + tid);
    __syncthreads();

    const int start = b * CHUNK;
    const int end   = (start + CHUNK < S) ? start + CHUNK : S;
    const float4* __restrict__ v4 = reinterpret_cast<const float4*>(sv);

    float m = NEG_INF, s = 0.f;
    float accp = 0.f;
    int   prev = -1;

    for (int r = start + warp; r < end; r += NWARP) {
        // 1) issue this row's 8 independent 16B streaming loads NOW
        const float4* __restrict__ r4 =
            reinterpret_cast<const float4*>(enc + (size_t)r * H);
        float4 a0 = __ldcs(&r4[0 * 32 + lane]);
        float4 a1 = __ldcs(&r4[1 * 32 + lane]);
        float4 a2 = __ldcs(&r4[2 * 32 + lane]);
        float4 a3 = __ldcs(&r4[3 * 32 + lane]);
        float4 a4 = __ldcs(&r4[4 * 32 + lane]);
        float4 a5 = __ldcs(&r4[5 * 32 + lane]);
        float4 a6 = __ldcs(&r4[6 * 32 + lane]);
        float4 a7 = __ldcs(&r4[7 * 32 + lane]);

        // 2) while they fly: finish the PREVIOUS row (shuffle + softmax)
        if (prev >= 0) {
            float acc = accp;
            #pragma unroll
            for (int o = 16; o > 0; o >>= 1)
                acc += __shfl_xor_sync(0xffffffffu, acc, o);
            if (lane == 0) ssc[prev] = acc;
            float nm = fmaxf(m, acc);
            s = s * __expf(m - nm) + __expf(acc - nm);
            m = nm;
        }

        // 3) consume the loads: 4-way split accumulator (short dep chains)
        float x0 = 0.f, x1 = 0.f, x2 = 0.f, x3 = 0.f;
        {
            float4 vv;
            vv = v4[0 * 32 + lane];
            x0 = fmaf(a0.x, vv.x, x0); x1 = fmaf(a0.y, vv.y, x1);
            x2 = fmaf(a0.z, vv.z, x2); x3 = fmaf(a0.w, vv.w, x3);
            vv = v4[1 * 32 + lane];
            x0 = fmaf(a1.x, vv.x, x0); x1 = fmaf(a1.y, vv.y, x1);
            x2 = fmaf(a1.z, vv.z, x2); x3 = fmaf(a1.w, vv.w, x3);
            vv = v4[2 * 32 + lane];
            x0 = fmaf(a2.x, vv.x, x0); x1 = fmaf(a2.y, vv.y, x1);
            x2 = fmaf(a2.z, vv.z, x2); x3 = fmaf(a2.w, vv.w, x3);
            vv = v4[3 * 32 + lane];
            x0 = fmaf(a3.x, vv.x, x0); x1 = fmaf(a3.y, vv.y, x1);
            x2 = fmaf(a3.z, vv.z, x2); x3 = fmaf(a3.w, vv.w, x3);
            vv = v4[4 * 32 + lane];
            x0 = fmaf(a4.x, vv.x, x0); x1 = fmaf(a4.y, vv.y, x1);
            x2 = fmaf(a4.z, vv.z, x2); x3 = fmaf(a4.w, vv.w, x3);
            vv = v4[5 * 32 + lane];
            x0 = fmaf(a5.x, vv.x, x0); x1 = fmaf(a5.y, vv.y, x1);
            x2 = fmaf(a5.z, vv.z, x2); x3 = fmaf(a5.w, vv.w, x3);
            vv = v4[6 * 32 + lane];
            x0 = fmaf(a6.x, vv.x, x0); x1 = fmaf(a6.y, vv.y, x1);
            x2 = fmaf(a6.z, vv.z, x2); x3 = fmaf(a6.w, vv.w, x3);
            vv = v4[7 * 32 + lane];
            x0 = fmaf(a7.x, vv.x, x0); x1 = fmaf(a7.y, vv.y, x1);
            x2 = fmaf(a7.z, vv.z, x2); x3 = fmaf(a7.w, vv.w, x3);
        }
        accp = (x0 + x1) + (x2 + x3);
        prev = r - start;
    }
    // drain the pipeline: last row's reduce
    if (prev >= 0) {
        float acc = accp;
        #pragma unroll
        for (int o = 16; o > 0; o >>= 1)
            acc += __shfl_xor_sync(0xffffffffu, acc, o);
        if (lane == 0) ssc[prev] = acc;
        float nm = fmaxf(m, acc);
        s = s * __expf(m - nm) + __expf(acc - nm);
        m = nm;
    }

    if (lane == 0) { smw[warp] = m; ssw[warp] = s; }
    __syncthreads();

    if (warp == 0) {                             // fixed-tree block merge
        float mm = smw[lane], sss = ssw[lane];
        #pragma unroll
        for (int o = 16; o > 0; o >>= 1) {
            float om = __shfl_xor_sync(0xffffffffu, mm, o);
            float os = __shfl_xor_sync(0xffffffffu, sss, o);
            float nm = fmaxf(mm, om);
            sss = sss * __expf(mm - nm) + os * __expf(om - nm);
            mm = nm;
        }
        if (lane == 0) { g_bm[b] = mm; g_bs[b] = sss; }
    }
    gbar(3);

    // ---------------- Phase 4: global merge + epilogue ----------------
    if (warp == 0) {                             // every block, redundantly
        float mm = NEG_INF, sss = 0.f;
        #pragma unroll
        for (int q = 0; q < 5; q++) {            // fixed order: deterministic
            int idx = lane + q * 32;
            if (idx < NBLK) {
                float om = __ldcg(&g_bm[idx]);
                float os = __ldcg(&g_bs[idx]);
                float nm = fmaxf(mm, om);
                sss = sss * __expf(mm - nm) + os * __expf(om - nm);
                mm = nm;
            }
        }
        #pragma unroll
        for (int o = 16; o > 0; o >>= 1) {
            float om = __shfl_xor_sync(0xffffffffu, mm, o);
            float os = __shfl_xor_sync(0xffffffffu, sss, o);
            float nm = fmaxf(mm, om);
            sss = sss * __expf(mm - nm) + os * __expf(om - nm);
            mm = nm;
        }
        if (lane == 0) { s_gm = mm; s_gs = sss; }
    }
    __syncthreads();

    const float gm  = s_gm;
    const float inv = 1.0f / s_gs;
    const int i = start + tid;                   // CHUNK=443 < 1024: one iter
    if (i < end) out[i] = __expf(ssc[i - start] - gm) * inv;
}

// ---------------------------------------------------------------------------
extern "C" void kernel_launch(void* const* d_in, const int* in_sizes, int n_in,
                              void* d_out, int out_size) {
    const float* hidden = (const float*)d_in[0];   // [H]
    const float* enc    = (const float*)d_in[1];   // [S, H]
    const float* W      = (const float*)d_in[2];   // [H, H]
    // d_in[3] = b : softmax-shift-invariant, unused
    float* out = (float*)d_out;                    // [1,1,S] fp32

    k0_reset<<<1, 1>>>();
    kmain<<<NBLK, THR>>>(hidden, enc, W, out);
}

// round 9
// speedup vs baseline: 2.3196x; 1.0457x over previous
#include <cuda_runtime.h>

#define H 1024
#define S 65536

// streaming geometry: warp-per-row, 16 rows per block
#define K2B   512
#define RPB   16
#define NB2   (S / RPB)        // 4096 streaming blocks

// k1 geometry
#define ISL   64               // W i-slices
#define IROWS (H / ISL)        // 16 rows each

// epilogue geometry
#define EB    64               // 64 blocks x 1024 threads, 1024 outputs each

#define NEG_INF (-3.402823466e38f)

// ---- device scratch (no allocation allowed) ----
__device__ float  g_vpart[ISL * H];
__device__ float  g_v[H];
__device__ float  g_scores[S];
__device__ float2 g_pairs[NB2];      // per-block online (max, expsum)

// ---------------------------------------------------------------------------
// k1: partial v over 64 i-slices. block b: 16 W-rows, all 1024 j's.
// ---------------------------------------------------------------------------
__global__ __launch_bounds__(1024) void k1_partial_v(const float* __restrict__ hidden,
                                                     const float* __restrict__ W) {
    const int i0 = blockIdx.x * IROWS;
    const int j  = threadIdx.x;
    float a0 = 0.f, a1 = 0.f, a2 = 0.f, a3 = 0.f;
    #pragma unroll
    for (int k = 0; k < IROWS; k += 4) {
        a0 = fmaf(__ldg(&hidden[i0 + k + 0]), W[(size_t)(i0 + k + 0) * H + j], a0);
        a1 = fmaf(__ldg(&hidden[i0 + k + 1]), W[(size_t)(i0 + k + 1) * H + j], a1);
        a2 = fmaf(__ldg(&hidden[i0 + k + 2]), W[(size_t)(i0 + k + 2) * H + j], a2);
        a3 = fmaf(__ldg(&hidden[i0 + k + 3]), W[(size_t)(i0 + k + 3) * H + j], a3);
    }
    g_vpart[blockIdx.x * H + j] = (a0 + a1) + (a2 + a3);
}

// k1b: v[j] = fixed-order sum of 64 partials. 4 blocks x 256.
__global__ __launch_bounds__(256) void k1b_reduce_v() {
    const int j = blockIdx.x * 256 + threadIdx.x;
    float a0 = 0.f, a1 = 0.f, a2 = 0.f, a3 = 0.f;
    #pragma unroll
    for (int s = 0; s < ISL; s += 4) {
        a0 += g_vpart[(s + 0) * H + j];
        a1 += g_vpart[(s + 1) * H + j];
        a2 += g_vpart[(s + 2) * H + j];
        a3 += g_vpart[(s + 3) * H + j];
    }
    g_v[j] = (a0 + a1) + (a2 + a3);
}

// ---------------------------------------------------------------------------
// k2: the 256 MB streaming pass. Warp-per-row, float4, evict-first loads.
// __launch_bounds__(512,4): regs capped at 32 -> 4 CTAs/SM -> 64 resident
// warps (the variable that R6-vs-R8 evidence says sets the DRAM duty cycle).
// Each block also emits one online softmax pair (deterministic fixed tree).
// ---------------------------------------------------------------------------
__global__ __launch_bounds__(K2B, 4) void k2_scores(const float* __restrict__ enc) {
    __shared__ float4 sv[H / 4];
    __shared__ float wsc[RPB];
    const int tid  = threadIdx.x;
    const int warp = tid >> 5;
    const int lane = tid & 31;

    if (tid < H / 4) sv[tid] = reinterpret_cast<const float4*>(g_v)[tid];
    __syncthreads();

    const int row = blockIdx.x * RPB + warp;
    const float4* __restrict__ r4 =
        reinterpret_cast<const float4*>(enc + (size_t)row * H);

    float x0 = 0.f, x1 = 0.f;
    #pragma unroll
    for (int k = 0; k < 8; k++) {
        float4 a  = __ldcs(&r4[k * 32 + lane]);
        float4 vv = sv[k * 32 + lane];
        x0 = fmaf(a.x, vv.x, x0);
        x1 = fmaf(a.y, vv.y, x1);
        x0 = fmaf(a.z, vv.z, x0);
        x1 = fmaf(a.w, vv.w, x1);
    }
    float acc = x0 + x1;
    #pragma unroll
    for (int o = 16; o > 0; o >>= 1)
        acc += __shfl_xor_sync(0xffffffffu, acc, o);

    if (lane == 0) {
        g_scores[row] = acc;
        wsc[warp] = acc;
    }
    __syncthreads();

    if (warp == 0 && lane < RPB) {           // 16 scores -> one (m, s) pair
        float sc = wsc[lane];
        float m = sc;
        #pragma unroll
        for (int o = 8; o > 0; o >>= 1)
            m = fmaxf(m, __shfl_xor_sync(0x0000ffffu, m, o));
        float e = __expf(sc - m);
        #pragma unroll
        for (int o = 8; o > 0; o >>= 1)
            e += __shfl_xor_sync(0x0000ffffu, e, o);
        if (lane == 0) g_pairs[blockIdx.x] = make_float2(m, e);
    }
}

// ---------------------------------------------------------------------------
// k3: fused epilogue. Each of 64 blocks redundantly merges the 4096 pairs
// (fixed-order: thread -> warp tree -> block tree; deterministic), then
// writes its 1024 normalized outputs straight from g_scores.
// ---------------------------------------------------------------------------
__global__ __launch_bounds__(1024) void k3_epilogue(float* __restrict__ out) {
    __shared__ float smw[32], sms[32];
    __shared__ float s_gm, s_gs;
    const int tid  = threadIdx.x;
    const int warp = tid >> 5;
    const int lane = tid & 31;

    // 4 pairs per thread, fixed order
    float m = NEG_INF, s = 0.f;
    #pragma unroll
    for (int q = 0; q < 4; q++) {
        float2 p = __ldcg(&g_pairs[tid * 4 + q]);
        float nm = fmaxf(m, p.x);
        s = s * __expf(m - nm) + p.y * __expf(p.x - nm);
        m = nm;
    }
    #pragma unroll
    for (int o = 16; o > 0; o >>= 1) {
        float om = __shfl_xor_sync(0xffffffffu, m, o);
        float os = __shfl_xor_sync(0xffffffffu, s, o);
        float nm = fmaxf(m, om);
        s = s * __expf(m - nm) + os * __expf(om - nm);
        m = nm;
    }
    if (lane == 0) { smw[warp] = m; sms[warp] = s; }
    __syncthreads();
    if (warp == 0) {
        float mm = smw[lane], ss = sms[lane];
        #pragma unroll
        for (int o = 16; o > 0; o >>= 1) {
            float om = __shfl_xor_sync(0xffffffffu, mm, o);
            float os = __shfl_xor_sync(0xffffffffu, ss, o);
            float nm = fmaxf(mm, om);
            ss = ss * __expf(mm - nm) + os * __expf(om - nm);
            mm = nm;
        }
        if (lane == 0) { s_gm = mm; s_gs = ss; }
    }
    __syncthreads();

    const float gm  = s_gm;
    const float inv = 1.0f / s_gs;
    const int i = blockIdx.x * 1024 + tid;
    out[i] = __expf(g_scores[i] - gm) * inv;
}

// ---------------------------------------------------------------------------
extern "C" void kernel_launch(void* const* d_in, const int* in_sizes, int n_in,
                              void* d_out, int out_size) {
    const float* hidden = (const float*)d_in[0];   // [H]
    const float* enc    = (const float*)d_in[1];   // [S, H]
    const float* W      = (const float*)d_in[2];   // [H, H]
    // d_in[3] = b : softmax-shift-invariant, unused
    float* out = (float*)d_out;                    // [1,1,S] fp32

    k1_partial_v<<<ISL, 1024>>>(hidden, W);
    k1b_reduce_v<<<H / 256, 256>>>();
    k2_scores<<<NB2, K2B>>>(enc);
    k3_epilogue<<<EB, 1024>>>(out);
}